// round 13
// baseline (speedup 1.0000x reference)
#include <cuda_runtime.h>
#include <cuda_bf16.h>

// img : (1, 64, 64, 1024) float32, NHWC
// rois: (1, 512, 4) int32  -> (x, y, w, h)
// out : (1, 512, 7, 7, 1024) float32
#define POOL   7
#define NROIS  512
#define IMG_W  64

typedef unsigned long long u64t;

// ---- packed f32x2 helpers (sm_103a) ----
__device__ __forceinline__ u64t pk(float v) {
    u64t r;
    asm("mov.b64 %0, {%1, %1};" : "=l"(r) : "f"(v));
    return r;
}
__device__ __forceinline__ u64t mul2(u64t a, u64t b) {
    u64t r;
    asm("mul.rn.f32x2 %0, %1, %2;" : "=l"(r) : "l"(a), "l"(b));
    return r;
}
__device__ __forceinline__ u64t fma2(u64t a, u64t b, u64t c) {
    u64t r;
    asm("fma.rn.f32x2 %0, %1, %2, %3;" : "=l"(r) : "l"(a), "l"(b), "l"(c));
    return r;
}

__device__ __forceinline__ void stg_cs(ulonglong2* p, ulonglong2 v) {
    asm volatile("st.global.cs.v2.b64 [%0], {%1, %2};"
                 :: "l"(p), "l"(v.x), "l"(v.y) : "memory");
}

__device__ __forceinline__ ulonglong2 blend2(ulonglong2 v00, ulonglong2 v01,
                                             ulonglong2 v10, ulonglong2 v11,
                                             float fx, float fy) {
    const float w11 = fx * fy;
    const float w01 = fx - w11;
    const float w10 = fy - w11;
    const float w00 = 1.0f - fx - w10;
    const u64t W00 = pk(w00), W01 = pk(w01), W10 = pk(w10), W11 = pk(w11);
    ulonglong2 o;
    o.x = fma2(v11.x, W11, fma2(v10.x, W10, fma2(v01.x, W01, mul2(v00.x, W00))));
    o.y = fma2(v11.y, W11, fma2(v10.y, W10, fma2(v01.y, W01, mul2(v00.y, W00))));
    return o;
}

// One CTA per (roi, py-pair). Rows pyA = 2*pid, pyB = min(pyA+1, 6); the two
// output rows read from up to 4 image rows, but B's rows frequently alias A's
// (y0b==y1a vertical sharing, always for small h) — aliased rows are served
// from registers. Horizontal left-column reuse (x0(px+1)==x1(px)) applies to
// every distinct row. All predicates are warp-uniform (ROI shared per CTA).
__global__ __launch_bounds__(256)
void roi_pool_kernel(const float* __restrict__ img,
                     const int*   __restrict__ rois,
                     float*       __restrict__ out)
{
    const int bid = blockIdx.x;            // roi*4 + pid
    const int roi = bid >> 2;
    const int pid = bid & 3;
    const int pyA = pid * 2;
    const int pyB = min(pyA + 1, POOL - 1);

    const int4 r = __ldg(((const int4*)rois) + roi);   // x, y, w, h

    const float stepx = (float)r.z / (float)POOL;
    const float stepy = (float)r.w / (float)POOL;
    const int   wm1 = r.z - 1;
    const int   hm1 = r.w - 1;

    // Row A y-work (reference fp32 arithmetic)
    const float syA = (float)pyA * stepy;
    const int   y0a = (int)syA;
    const float fyA = syA - (float)y0a;
    const int   y1a = min(y0a + 1, hm1);
    // Row B y-work
    const float syB = (float)pyB * stepy;
    const int   y0b = (int)syB;
    const float fyB = syB - (float)y0b;
    const int   y1b = min(y0b + 1, hm1);

    // Warp-uniform row-aliasing predicates
    const bool b0_is_a1 = (y0b == y1a);
    const bool b0_is_a0 = (y0b == y0a);
    const bool b1_is_a1 = (y1b == y1a);

    const int c = threadIdx.x;             // 0..255 float4 lane
    const ulonglong2* ibase = (const ulonglong2*)img;
    const unsigned base = (unsigned)(r.y * IMG_W + r.x) * 256u + c;
    const unsigned rA0 = base + (unsigned)(y0a * IMG_W) * 256u;
    const unsigned rA1 = base + (unsigned)(y1a * IMG_W) * 256u;
    const unsigned rB0 = base + (unsigned)(y0b * IMG_W) * 256u;
    const unsigned rB1 = base + (unsigned)(y1b * IMG_W) * 256u;

    ulonglong2* optrA = (ulonglong2*)out + ((size_t)(roi * (POOL*POOL) + pyA * POOL)) * 256 + c;
    ulonglong2* optrB = (ulonglong2*)out + ((size_t)(roi * (POOL*POOL) + pyB * POOL)) * 256 + c;
    const bool storeB = (pyB != pyA);

    // Per-row left/right column values
    ulonglong2 vA0l, vA0r, vA1l, vA1r, vB0l, vB0r, vB1l, vB1r;

    float fxc = 0.0f;
    unsigned prev_x1 = (unsigned)min(1, wm1);

    // ---- px = 0: load both columns of every distinct row ----
    {
        const unsigned u1 = prev_x1 * 256u;
        vA0l = __ldg(ibase + rA0);
        vA0r = __ldg(ibase + rA0 + u1);
        vA1l = __ldg(ibase + rA1);
        vA1r = __ldg(ibase + rA1 + u1);
        if (b0_is_a1)      { vB0l = vA1l; vB0r = vA1r; }
        else if (b0_is_a0) { vB0l = vA0l; vB0r = vA0r; }
        else { vB0l = __ldg(ibase + rB0); vB0r = __ldg(ibase + rB0 + u1); }
        if (b1_is_a1)      { vB1l = vA1l; vB1r = vA1r; }
        else { vB1l = __ldg(ibase + rB1); vB1r = __ldg(ibase + rB1 + u1); }
    }

    #pragma unroll
    for (int px = 0; px < POOL; ++px) {
        // blend + store current cell pair
        stg_cs(optrA, blend2(vA0l, vA0r, vA1l, vA1r, fxc, fyA));
        optrA += 256;
        if (storeB) {
            stg_cs(optrB, blend2(vB0l, vB0r, vB1l, vB1r, fxc, fyB));
            optrB += 256;
        }

        if (px + 1 < POOL) {
            const float sx  = (float)(px + 1) * stepx;
            const int   x0  = (int)sx;
            fxc = sx - (float)x0;
            const unsigned x1n = (unsigned)min(x0 + 1, wm1);
            const unsigned u0 = (unsigned)x0 * 256u;
            const unsigned u1 = x1n * 256u;
            const bool hreuse = ((unsigned)x0 == prev_x1);   // warp-uniform
            prev_x1 = x1n;

            // A rows: horizontal reuse of left column, load right
            vA0l = hreuse ? vA0r : __ldg(ibase + rA0 + u0);
            vA0r = __ldg(ibase + rA0 + u1);
            vA1l = hreuse ? vA1r : __ldg(ibase + rA1 + u0);
            vA1r = __ldg(ibase + rA1 + u1);

            // B rows: vertical alias from A when rows coincide, else own loads
            if (b0_is_a1)      { vB0l = vA1l; vB0r = vA1r; }
            else if (b0_is_a0) { vB0l = vA0l; vB0r = vA0r; }
            else {
                vB0l = hreuse ? vB0r : __ldg(ibase + rB0 + u0);
                vB0r = __ldg(ibase + rB0 + u1);
            }
            if (b1_is_a1)      { vB1l = vA1l; vB1r = vA1r; }
            else {
                vB1l = hreuse ? vB1r : __ldg(ibase + rB1 + u0);
                vB1r = __ldg(ibase + rB1 + u1);
            }
        }
    }
}

extern "C" void kernel_launch(void* const* d_in, const int* in_sizes, int n_in,
                              void* d_out, int out_size)
{
    const float* img  = (const float*)d_in[0];
    const int*   rois = (const int*)d_in[1];
    float*       out  = (float*)d_out;

    const int grid = NROIS * 4;           // 2048 CTAs, one per (roi, py-pair)
    roi_pool_kernel<<<grid, 256>>>(img, rois, out);
}

// round 14
// speedup vs baseline: 1.0714x; 1.0714x over previous
#include <cuda_runtime.h>
#include <cuda_bf16.h>

// img : (1, 64, 64, 1024) float32, NHWC
// rois: (1, 512, 4) int32  -> (x, y, w, h)
// out : (1, 512, 7, 7, 1024) float32
#define POOL   7
#define NROIS  512
#define IMG_W  64

typedef unsigned long long u64t;

// ---- packed f32x2 helpers (sm_103a) ----
__device__ __forceinline__ u64t pk(float v) {
    u64t r;
    asm("mov.b64 %0, {%1, %1};" : "=l"(r) : "f"(v));
    return r;
}
__device__ __forceinline__ u64t mul2(u64t a, u64t b) {
    u64t r;
    asm("mul.rn.f32x2 %0, %1, %2;" : "=l"(r) : "l"(a), "l"(b));
    return r;
}
__device__ __forceinline__ u64t fma2(u64t a, u64t b, u64t c) {
    u64t r;
    asm("fma.rn.f32x2 %0, %1, %2, %3;" : "=l"(r) : "l"(a), "l"(b), "l"(c));
    return r;
}

// 16B streaming store (output never re-read) — don't pollute L1.
__device__ __forceinline__ void stg_cs(ulonglong2* p, ulonglong2 v) {
    asm volatile("st.global.cs.v2.b64 [%0], {%1, %2};"
                 :: "l"(p), "l"(v.x), "l"(v.y) : "memory");
}

__device__ __forceinline__ ulonglong2 blend2(ulonglong2 v00, ulonglong2 v01,
                                             ulonglong2 v10, ulonglong2 v11,
                                             float fx, float fy) {
    const float w11 = fx * fy;
    const float w01 = fx - w11;          // fx*(1-fy)
    const float w10 = fy - w11;          // (1-fx)*fy
    const float w00 = 1.0f - fx - w10;   // (1-fx)*(1-fy)
    const u64t W00 = pk(w00), W01 = pk(w01), W10 = pk(w10), W11 = pk(w11);
    ulonglong2 o;
    o.x = fma2(v11.x, W11, fma2(v10.x, W10, fma2(v01.x, W01, mul2(v00.x, W00))));
    o.y = fma2(v11.y, W11, fma2(v10.y, W10, fma2(v01.y, W01, mul2(v00.y, W00))));
    return o;
}

// One CTA per (roi, py) output row: 7 px cells, 256 threads, 1 float4 lane
// each. Depth-1 software pipeline over px with warp-uniform horizontal
// register reuse (x0(px+1)==x1(px) -> left column served from registers).
// Right-column loads issued first (always needed); full L1 carveout.
__global__ __launch_bounds__(256)
void roi_pool_kernel(const float* __restrict__ img,
                     const int*   __restrict__ rois,
                     float*       __restrict__ out)
{
    const int bid = blockIdx.x;           // roi*7 + py
    const int roi = bid / POOL;
    const int py  = bid - roi * POOL;

    const int4 r = __ldg(((const int4*)rois) + roi);   // x, y, w, h

    // Loop-invariant y-axis work (match reference fp32 arithmetic exactly)
    const float stepx = (float)r.z / (float)POOL;
    const float sy = (float)py * ((float)r.w / (float)POOL);
    const int   y0 = (int)sy;
    const float fy = sy - (float)y0;
    const int   y1 = min(y0 + 1, r.w - 1);
    const int   wm1 = r.z - 1;

    const int c = threadIdx.x;            // 0..255 float4 lane
    const ulonglong2* row0 = (const ulonglong2*)img
                           + (unsigned)((r.y + y0) * IMG_W + r.x) * 256u + c;
    const ulonglong2* row1 = (const ulonglong2*)img
                           + (unsigned)((r.y + y1) * IMG_W + r.x) * 256u + c;

    ulonglong2* optr = (ulonglong2*)out + ((size_t)bid * POOL) * 256 + c;

    // ---- prologue: px = 0 (sx = 0, x0 = 0, fx = 0) ----
    float fxc = 0.0f;
    unsigned prev_x1 = (unsigned)min(1, wm1);   // current cell's right column
    {
        const unsigned x1u = prev_x1 * 256u;
        ulonglong2 a01 = __ldg(row0 + x1u);
        ulonglong2 a11 = __ldg(row1 + x1u);
        ulonglong2 a00 = __ldg(row0);
        ulonglong2 a10 = __ldg(row1);

        #pragma unroll
        for (int px = 1; px < POOL; ++px) {
            const float sx  = (float)px * stepx;
            const int   x0  = (int)sx;
            const float fxn = sx - (float)x0;
            const unsigned x1n = (unsigned)min(x0 + 1, wm1);
            const unsigned u0 = (unsigned)x0 * 256u;
            const unsigned u1 = x1n * 256u;
            const bool reuse = ((unsigned)x0 == prev_x1);   // warp-uniform

            // Right column first (always loaded), then left (maybe from regs)
            const ulonglong2 b01 = __ldg(row0 + u1);
            const ulonglong2 b11 = __ldg(row1 + u1);
            ulonglong2 b00, b10;
            if (reuse) { b00 = a01; b10 = a11; }
            else       { b00 = __ldg(row0 + u0);
                         b10 = __ldg(row1 + u0); }

            stg_cs(optr, blend2(a00, a01, a10, a11, fxc, fy));
            optr += 256;

            a00 = b00; a01 = b01; a10 = b10; a11 = b11;
            fxc = fxn;
            prev_x1 = x1n;
        }

        // ---- epilogue: px = 6 ----
        stg_cs(optr, blend2(a00, a01, a10, a11, fxc, fy));
    }
}

extern "C" void kernel_launch(void* const* d_in, const int* in_sizes, int n_in,
                              void* d_out, int out_size)
{
    const float* img  = (const float*)d_in[0];
    const int*   rois = (const int*)d_in[1];
    float*       out  = (float*)d_out;

    // Kernel uses no shared memory: ask for the maximum L1 carveout so the
    // bilinear read stream gets the full 228KB of L1 (raises hit rate).
    cudaFuncSetAttribute(roi_pool_kernel,
                         cudaFuncAttributePreferredSharedMemoryCarveout,
                         cudaSharedmemCarveoutMaxL1);

    const int grid = NROIS * POOL;        // 3584 CTAs, one per (roi, py)
    roi_pool_kernel<<<grid, 256>>>(img, rois, out);
}

// round 15
// speedup vs baseline: 1.0750x; 1.0033x over previous
#include <cuda_runtime.h>
#include <cuda_bf16.h>

// img : (1, 64, 64, 1024) float32, NHWC
// rois: (1, 512, 4) int32  -> (x, y, w, h)
// out : (1, 512, 7, 7, 1024) float32
#define POOL   7
#define NROIS  512
#define IMG_W  64

typedef unsigned long long u64t;

// ---- packed f32x2 helpers (sm_103a) ----
__device__ __forceinline__ u64t pk(float v) {
    u64t r;
    asm("mov.b64 %0, {%1, %1};" : "=l"(r) : "f"(v));
    return r;
}
__device__ __forceinline__ u64t mul2(u64t a, u64t b) {
    u64t r;
    asm("mul.rn.f32x2 %0, %1, %2;" : "=l"(r) : "l"(a), "l"(b));
    return r;
}
__device__ __forceinline__ u64t fma2(u64t a, u64t b, u64t c) {
    u64t r;
    asm("fma.rn.f32x2 %0, %1, %2, %3;" : "=l"(r) : "l"(a), "l"(b), "l"(c));
    return r;
}

// 16B streaming store (output never re-read) — don't pollute L1.
__device__ __forceinline__ void stg_cs(ulonglong2* p, ulonglong2 v) {
    asm volatile("st.global.cs.v2.b64 [%0], {%1, %2};"
                 :: "l"(p), "l"(v.x), "l"(v.y) : "memory");
}

__device__ __forceinline__ ulonglong2 blend2(ulonglong2 v00, ulonglong2 v01,
                                             ulonglong2 v10, ulonglong2 v11,
                                             float fx, float fy) {
    const float w11 = fx * fy;
    const float w01 = fx - w11;          // fx*(1-fy)
    const float w10 = fy - w11;          // (1-fx)*fy
    const float w00 = 1.0f - fx - w10;   // (1-fx)*(1-fy)
    const u64t W00 = pk(w00), W01 = pk(w01), W10 = pk(w10), W11 = pk(w11);
    ulonglong2 o;
    o.x = fma2(v11.x, W11, fma2(v10.x, W10, fma2(v01.x, W01, mul2(v00.x, W00))));
    o.y = fma2(v11.y, W11, fma2(v10.y, W10, fma2(v01.y, W01, mul2(v00.y, W00))));
    return o;
}

// 512-thread CTA = two independent 256-thread halves, each producing one
// output row (roi, py). Flat row index: row = 2*bid + (tid>=256) — perfect
// balance; ~86% of halves are same-roi adjacent-py pairs whose image rows
// frequently coincide, so the second half's loads HIT L1 on the same SM
// (hardware bid->SM scattering otherwise duplicates these fills across SMs).
// Each half: depth-1 px pipeline, warp-uniform horizontal register reuse,
// packed-f32x2 blend, streaming stores.
__global__ __launch_bounds__(512)
void roi_pool_kernel(const float* __restrict__ img,
                     const int*   __restrict__ rois,
                     float*       __restrict__ out)
{
    const int row = blockIdx.x * 2 + (threadIdx.x >> 8);  // 0..3583
    const int roi = row / POOL;
    const int py  = row - roi * POOL;

    const int4 r = __ldg(((const int4*)rois) + roi);   // x, y, w, h

    // Loop-invariant y-axis work (match reference fp32 arithmetic exactly)
    const float stepx = (float)r.z / (float)POOL;
    const float sy = (float)py * ((float)r.w / (float)POOL);
    const int   y0 = (int)sy;
    const float fy = sy - (float)y0;
    const int   y1 = min(y0 + 1, r.w - 1);
    const int   wm1 = r.z - 1;

    const int c = threadIdx.x & 255;      // 0..255 float4 lane
    const ulonglong2* row0 = (const ulonglong2*)img
                           + (unsigned)((r.y + y0) * IMG_W + r.x) * 256u + c;
    const ulonglong2* row1 = (const ulonglong2*)img
                           + (unsigned)((r.y + y1) * IMG_W + r.x) * 256u + c;

    ulonglong2* optr = (ulonglong2*)out + ((size_t)row * POOL) * 256 + c;

    // ---- prologue: px = 0 (sx = 0, x0 = 0, fx = 0) ----
    float fxc = 0.0f;
    unsigned prev_x1 = (unsigned)min(1, wm1);   // current cell's right column
    {
        const unsigned x1u = prev_x1 * 256u;
        ulonglong2 a01 = __ldg(row0 + x1u);
        ulonglong2 a11 = __ldg(row1 + x1u);
        ulonglong2 a00 = __ldg(row0);
        ulonglong2 a10 = __ldg(row1);

        #pragma unroll
        for (int px = 1; px < POOL; ++px) {
            const float sx  = (float)px * stepx;
            const int   x0  = (int)sx;
            const float fxn = sx - (float)x0;
            const unsigned x1n = (unsigned)min(x0 + 1, wm1);
            const unsigned u0 = (unsigned)x0 * 256u;
            const unsigned u1 = x1n * 256u;
            const bool reuse = ((unsigned)x0 == prev_x1);   // warp-uniform

            // Right column first (always loaded), then left (maybe from regs)
            const ulonglong2 b01 = __ldg(row0 + u1);
            const ulonglong2 b11 = __ldg(row1 + u1);
            ulonglong2 b00, b10;
            if (reuse) { b00 = a01; b10 = a11; }
            else       { b00 = __ldg(row0 + u0);
                         b10 = __ldg(row1 + u0); }

            stg_cs(optr, blend2(a00, a01, a10, a11, fxc, fy));
            optr += 256;

            a00 = b00; a01 = b01; a10 = b10; a11 = b11;
            fxc = fxn;
            prev_x1 = x1n;
        }

        // ---- epilogue: px = 6 ----
        stg_cs(optr, blend2(a00, a01, a10, a11, fxc, fy));
    }
}

extern "C" void kernel_launch(void* const* d_in, const int* in_sizes, int n_in,
                              void* d_out, int out_size)
{
    const float* img  = (const float*)d_in[0];
    const int*   rois = (const int*)d_in[1];
    float*       out  = (float*)d_out;

    // No shared memory used: maximize the L1 carveout (raises hit rate of the
    // bilinear read stream and the cross-half row sharing).
    cudaFuncSetAttribute(roi_pool_kernel,
                         cudaFuncAttributePreferredSharedMemoryCarveout,
                         cudaSharedmemCarveoutMaxL1);

    const int grid = (NROIS * POOL * POOL) / 14;   // 1792 CTAs, 2 rows each
    roi_pool_kernel<<<grid, 512>>>(img, rois, out);
}